// round 11
// baseline (speedup 1.0000x reference)
#include <cuda_runtime.h>
#include <math.h>

#define B 2048
#define C 1024
#define NSM 148   // persistent-kernel block count (< 152 SMs -> always co-resident)

// ---- scratch (device globals; no dynamic allocation allowed) ----
__device__ float g_ps[(size_t)B * C];        // softmax(y_s/2)
__device__ float g_pt[(size_t)B * C];        // softmax(y_t/2)
__device__ float g_W [(size_t)B * B];        // pairwise L1 distances
__device__ float g_K [(size_t)B * B];        // exp(-W/eps)
__device__ float g_KT[(size_t)B * B];        // K transposed (written by wxy epilogue)
__device__ float g_u[B];
__device__ float g_v[B];
__device__ float g_partial[B];
__device__ unsigned g_bar;                   // grid-barrier arrival counter

// ---------------- block reductions (256 threads, deterministic) ----------------
__device__ __forceinline__ float blockReduceSum(float v) {
    __shared__ float sh[8];
    int lane = threadIdx.x & 31;
    int wid  = threadIdx.x >> 5;
#pragma unroll
    for (int o = 16; o > 0; o >>= 1) v += __shfl_xor_sync(0xffffffffu, v, o);
    __syncthreads();                 // protect sh against reuse across calls
    if (lane == 0) sh[wid] = v;
    __syncthreads();
    float r = sh[0];
#pragma unroll
    for (int w = 1; w < 8; w++) r += sh[w];
    return r;                        // same value in every thread
}

__device__ __forceinline__ float blockReduceMax(float v) {
    __shared__ float sh[8];
    int lane = threadIdx.x & 31;
    int wid  = threadIdx.x >> 5;
#pragma unroll
    for (int o = 16; o > 0; o >>= 1) v = fmaxf(v, __shfl_xor_sync(0xffffffffu, v, o));
    __syncthreads();
    if (lane == 0) sh[wid] = v;
    __syncthreads();
    float r = sh[0];
#pragma unroll
    for (int w = 1; w < 8; w++) r = fmaxf(r, sh[w]);
    return r;
}

// ---------------- softmax(x/2) per row (both tensors in one grid) ----------------
// Block 0 additionally resets Sinkhorn state (v=1, barrier counter=0) for this
// replay; consumers run in later, stream-serialized kernels.
__global__ void __launch_bounds__(256) softmax_kernel(const float* __restrict__ ys,
                                                      const float* __restrict__ yt) {
    if (blockIdx.x == 0) {
#pragma unroll
        for (int i = threadIdx.x; i < B; i += 256) g_v[i] = 1.0f;
        if (threadIdx.x == 0) g_bar = 0u;
    }

    int which = blockIdx.x >= B;
    int row   = blockIdx.x - (which ? B : 0);
    const float* in  = which ? yt : ys;
    float*       out = which ? g_pt : g_ps;
    const float4* x4 = (const float4*)(in + (size_t)row * C);
    float4*       o4 = (float4*)(out + (size_t)row * C);

    float4 xv = x4[threadIdx.x];                  // 256 threads * 4 = 1024
    float z[4] = {xv.x * 0.5f, xv.y * 0.5f, xv.z * 0.5f, xv.w * 0.5f};
    float m = fmaxf(fmaxf(z[0], z[1]), fmaxf(z[2], z[3]));
    m = blockReduceMax(m);

    float e[4], s = 0.f;
#pragma unroll
    for (int k = 0; k < 4; k++) { e[k] = expf(z[k] - m); s += e[k]; }
    s = blockReduceSum(s);
    float inv = 1.0f / s;
    o4[threadIdx.x] = make_float4(e[0] * inv, e[1] * inv, e[2] * inv, e[3] * inv);
}

// ---------------- pairwise L1 distance + K = exp(-W/eps) + KT ----------------
// Identity: softmax rows sum to 1, so
//   W[i][j] = sum_c |ps - pt| = 2 - 2 * sum_c min(ps, pt)
// Inner loop: FMNMX (alu pipe) + FADD (fma pipe), both rt=2 -> the SMSP
// issue port alternates pipes at 1 instr/cyc => ~2 cyc per element-pair.
// Tile: 128(i) x 64(j) per block, 256 threads, 8x4 register tile per thread,
// C in chunks of 16: 3 LDS.128 + 64 math per 32 pairs = 2.09 issue/pair.
// Double-buffered smem + software pipelining: per chunk, prefetch chunk i+1,
// compute chunk i from buf[cur], store prefetched regs to buf[cur^1], ONE
// __syncthreads. LDG latency retires fully under the ~1072-cycle compute
// block; barrier count halves vs the single-buffer scheme.
// Epilogue writes W, K row-major AND K^T directly (8 contiguous i per j),
// eliminating the separate transpose pass.
__global__ void __launch_bounds__(256) wxy_kernel() {
    __shared__ __align__(16) float As[2][16][128];
    __shared__ __align__(16) float Bs[2][16][64];

    const int i0 = blockIdx.y * 128;
    const int j0 = blockIdx.x * 64;
    const int tid = threadIdx.x;
    const int tx = tid & 15;        // j group: cols j0 + tx*4 .. +3
    const int ty = tid >> 4;        // i group: rows i0 + ty*8 .. +7

    // A staging: 512 float4 per chunk -> threads load f = tid and tid+256
    const int ar0 = tid >> 2;              // row of first A float4   (0..63)
    const int ar1 = (tid + 256) >> 2;      // row of second A float4  (64..127)
    const int acq = tid & 3;               // float4 index within 16-c chunk
    // B staging: 256 float4 per chunk -> thread loads f = tid
    const int br  = tid >> 2;              // 0..63
    const int bcq = tid & 3;

    const float* pa0 = &g_ps[(size_t)(i0 + ar0) * C + acq * 4];
    const float* pa1 = &g_ps[(size_t)(i0 + ar1) * C + acq * 4];
    const float* pb  = &g_pt[(size_t)(j0 + br ) * C + bcq * 4];

    float acc[8][4];
#pragma unroll
    for (int m = 0; m < 8; m++)
#pragma unroll
        for (int n = 0; n < 4; n++) acc[m][n] = 0.f;

    // Prologue: load chunk 0, stage into buffer 0.
    {
        float4 a40 = *(const float4*)(pa0);
        float4 a41 = *(const float4*)(pa1);
        float4 b4  = *(const float4*)(pb);
        As[0][acq * 4 + 0][ar0] = a40.x;  As[0][acq * 4 + 1][ar0] = a40.y;
        As[0][acq * 4 + 2][ar0] = a40.z;  As[0][acq * 4 + 3][ar0] = a40.w;
        As[0][acq * 4 + 0][ar1] = a41.x;  As[0][acq * 4 + 1][ar1] = a41.y;
        As[0][acq * 4 + 2][ar1] = a41.z;  As[0][acq * 4 + 3][ar1] = a41.w;
        Bs[0][bcq * 4 + 0][br] = b4.x;  Bs[0][bcq * 4 + 1][br] = b4.y;
        Bs[0][bcq * 4 + 2][br] = b4.z;  Bs[0][bcq * 4 + 3][br] = b4.w;
    }
    __syncthreads();

    int cur = 0;
    for (int c0 = 0; c0 < C; c0 += 16) {
        const bool more = (c0 + 16 < C);
        float4 a40, a41, b4;
        if (more) {                 // prefetch chunk i+1 (hides under compute)
            a40 = *(const float4*)(pa0 + c0 + 16);
            a41 = *(const float4*)(pa1 + c0 + 16);
            b4  = *(const float4*)(pb  + c0 + 16);
        }

#pragma unroll
        for (int c = 0; c < 16; c++) {
            float a[8], b[4];
            *(float4*)&a[0] = *(const float4*)&As[cur][c][ty * 8];
            *(float4*)&a[4] = *(const float4*)&As[cur][c][ty * 8 + 4];
            *(float4*)&b[0] = *(const float4*)&Bs[cur][c][tx * 4];
#pragma unroll
            for (int m = 0; m < 8; m++)
#pragma unroll
                for (int n = 0; n < 4; n++)
                    acc[m][n] += fminf(a[m], b[n]);
        }

        if (more) {                 // stage chunk i+1 into the other buffer
            int nxt = cur ^ 1;
            As[nxt][acq * 4 + 0][ar0] = a40.x;  As[nxt][acq * 4 + 1][ar0] = a40.y;
            As[nxt][acq * 4 + 2][ar0] = a40.z;  As[nxt][acq * 4 + 3][ar0] = a40.w;
            As[nxt][acq * 4 + 0][ar1] = a41.x;  As[nxt][acq * 4 + 1][ar1] = a41.y;
            As[nxt][acq * 4 + 2][ar1] = a41.z;  As[nxt][acq * 4 + 3][ar1] = a41.w;
            Bs[nxt][bcq * 4 + 0][br] = b4.x;  Bs[nxt][bcq * 4 + 1][br] = b4.y;
            Bs[nxt][bcq * 4 + 2][br] = b4.z;  Bs[nxt][bcq * 4 + 3][br] = b4.w;
            __syncthreads();        // all reads of buf[cur] & writes of buf[nxt] done
            cur = nxt;
        }
    }

    // Epilogue: W and K row-major; K values overwrite acc[][] in place.
#pragma unroll
    for (int m = 0; m < 8; m++) {
        int i = i0 + ty * 8 + m;
        size_t base = (size_t)i * B + j0 + tx * 4;
        float w0 = 2.0f - 2.0f * acc[m][0];
        float w1 = 2.0f - 2.0f * acc[m][1];
        float w2 = 2.0f - 2.0f * acc[m][2];
        float w3 = 2.0f - 2.0f * acc[m][3];
        *(float4*)&g_W[base] = make_float4(w0, w1, w2, w3);
        acc[m][0] = expf(-10.f * w0);
        acc[m][1] = expf(-10.f * w1);
        acc[m][2] = expf(-10.f * w2);
        acc[m][3] = expf(-10.f * w3);
        *(float4*)&g_K[base] = make_float4(acc[m][0], acc[m][1], acc[m][2], acc[m][3]);
    }
    // KT: for each j, the 8 i-values are contiguous -> two STG.128 per j.
#pragma unroll
    for (int n = 0; n < 4; n++) {
        int j = j0 + tx * 4 + n;
        size_t base = (size_t)j * B + i0 + ty * 8;
        *(float4*)&g_KT[base]     = make_float4(acc[0][n], acc[1][n], acc[2][n], acc[3][n]);
        *(float4*)&g_KT[base + 4] = make_float4(acc[4][n], acc[5][n], acc[6][n], acc[7][n]);
    }
}

// ---------------- persistent Sinkhorn + fused loss ----------------
// Grid barrier: monotonic counter; each instance waits for the next multiple
// of NSM. Counter reset in softmax_kernel every replay -> deterministic graph
// replays. NSM=148 blocks x 256 thr are always co-resident (152 SMs).
__device__ __forceinline__ void grid_barrier() {
    __syncthreads();
    if (threadIdx.x == 0) {
        __threadfence();                                  // publish my writes
        unsigned t = atomicAdd(&g_bar, 1u) + 1u;
        unsigned target = ((t + NSM - 1u) / NSM) * NSM;   // end of this instance
        while (*(volatile unsigned*)&g_bar < target) __nanosleep(32);
        __threadfence();                                  // acquire others' writes
    }
    __syncthreads();
}

// Warp-per-row dot product: 16 independent LDG.128 per lane (MLP=16), then a
// 5-shuffle warp reduce. No per-row __syncthreads -> latency fully hidden by
// 8 rows in flight per block; each phase is L2-bandwidth-bound (~1.3us).
__device__ __forceinline__ float warpDotRow(const float* __restrict__ M,
                                            const float* __restrict__ x, int row) {
    const float4* M4 = (const float4*)(M + (size_t)row * B);
    const float4* x4 = (const float4*)x;
    const int lane = threadIdx.x & 31;
    float s = 0.f;
#pragma unroll
    for (int k = 0; k < 16; k++) {
        float4 m  = M4[lane + k * 32];
        float4 xv = x4[lane + k * 32];
        s += m.x * xv.x + m.y * xv.y + m.z * xv.z + m.w * xv.w;
    }
#pragma unroll
    for (int o = 16; o > 0; o >>= 1) s += __shfl_xor_sync(0xffffffffu, s, o);
    return s;                        // same value in all lanes
}

__global__ void __launch_bounds__(256) sinkhorn_kernel(float* __restrict__ out) {
    const int wid   = threadIdx.x >> 5;                 // 0..7
    const int lane  = threadIdx.x & 31;
    const int wrow0 = blockIdx.x * 8 + wid;             // warp-global row start
    const int wstep = NSM * 8;                          // 1184 warps total

    for (int iter = 0; iter < 20; iter++) {
        // u = 1 / (K v)
        for (int row = wrow0; row < B; row += wstep) {
            float s = warpDotRow(g_K, g_v, row);
            if (lane == 0) g_u[row] = 1.0f / s;
        }
        grid_barrier();
        // v = 1 / (K^T u)
        for (int row = wrow0; row < B; row += wstep) {
            float s = warpDotRow(g_KT, g_u, row);
            if (lane == 0) g_v[row] = 1.0f / s;
        }
        grid_barrier();
    }

    // ---- fused loss: 0.001 * sum_ij u_i K_ij W_ij v_j (K, W are L2-hot) ----
    for (int row = wrow0; row < B; row += wstep) {
        const float4* K4 = (const float4*)(g_K + (size_t)row * B);
        const float4* W4 = (const float4*)(g_W + (size_t)row * B);
        const float4* v4 = (const float4*)g_v;
        float s = 0.f;
#pragma unroll
        for (int k = 0; k < 16; k++) {
            float4 kk = K4[lane + k * 32];
            float4 ww = W4[lane + k * 32];
            float4 vv = v4[lane + k * 32];
            s += kk.x * ww.x * vv.x + kk.y * ww.y * vv.y
               + kk.z * ww.z * vv.z + kk.w * ww.w * vv.w;
        }
#pragma unroll
        for (int o = 16; o > 0; o >>= 1) s += __shfl_xor_sync(0xffffffffu, s, o);
        if (lane == 0) g_partial[row] = g_u[row] * s;
    }
    grid_barrier();

    if (blockIdx.x == 0) {                      // deterministic final reduce
        float s = 0.f;
        for (int i = threadIdx.x; i < B; i += 256) s += g_partial[i];
        s = blockReduceSum(s);
        if (threadIdx.x == 0) out[0] = 0.001f * s;
    }
}

// ---------------- launch ----------------
extern "C" void kernel_launch(void* const* d_in, const int* in_sizes, int n_in,
                              void* d_out, int out_size) {
    const float* y_s = (const float*)d_in[0];
    const float* y_t = (const float*)d_in[1];
    float* out = (float*)d_out;

    softmax_kernel<<<2 * B, 256>>>(y_s, y_t);
    wxy_kernel<<<dim3(B / 64, B / 128), 256>>>();
    sinkhorn_kernel<<<NSM, 256>>>(out);
}

// round 13
// speedup vs baseline: 1.4557x; 1.4557x over previous
#include <cuda_runtime.h>
#include <cuda_fp16.h>
#include <math.h>

#define B 2048
#define C 1024
#define NSM 148   // persistent-kernel block count (< 152 SMs -> always co-resident)

// ---- scratch (device globals; no dynamic allocation allowed) ----
__device__ __align__(16) unsigned g_psh[(size_t)B * C / 2];  // half2-packed softmax(y_s/2)
__device__ __align__(16) unsigned g_pth[(size_t)B * C / 2];  // half2-packed softmax(y_t/2)
__device__ float g_W [(size_t)B * B];        // pairwise L1 distances
__device__ float g_K [(size_t)B * B];        // exp(-W/eps)
__device__ float g_KT[(size_t)B * B];        // K transposed (written by wxy epilogue)
__device__ float g_u[B];
__device__ float g_v[B];
__device__ float g_partial[B];
__device__ unsigned g_bar;                   // grid-barrier arrival counter

// ---------------- block reductions (256 threads, deterministic) ----------------
__device__ __forceinline__ float blockReduceSum(float v) {
    __shared__ float sh[8];
    int lane = threadIdx.x & 31;
    int wid  = threadIdx.x >> 5;
#pragma unroll
    for (int o = 16; o > 0; o >>= 1) v += __shfl_xor_sync(0xffffffffu, v, o);
    __syncthreads();
    if (lane == 0) sh[wid] = v;
    __syncthreads();
    float r = sh[0];
#pragma unroll
    for (int w = 1; w < 8; w++) r += sh[w];
    return r;
}

__device__ __forceinline__ float blockReduceMax(float v) {
    __shared__ float sh[8];
    int lane = threadIdx.x & 31;
    int wid  = threadIdx.x >> 5;
#pragma unroll
    for (int o = 16; o > 0; o >>= 1) v = fmaxf(v, __shfl_xor_sync(0xffffffffu, v, o));
    __syncthreads();
    if (lane == 0) sh[wid] = v;
    __syncthreads();
    float r = sh[0];
#pragma unroll
    for (int w = 1; w < 8; w++) r = fmaxf(r, sh[w]);
    return r;
}

// ---------------- softmax(x/2) per row -> half2-packed output ----------------
// Block 0 additionally resets Sinkhorn state (v=1, barrier counter=0).
__global__ void __launch_bounds__(256) softmax_kernel(const float* __restrict__ ys,
                                                      const float* __restrict__ yt) {
    if (blockIdx.x == 0) {
        for (int i = threadIdx.x; i < B; i += 256) g_v[i] = 1.0f;
        if (threadIdx.x == 0) g_bar = 0u;
    }

    int which = blockIdx.x >= B;
    int row   = blockIdx.x - (which ? B : 0);
    const float* in = which ? yt : ys;
    unsigned*   outh = which ? g_pth : g_psh;
    const float4* x4 = (const float4*)(in + (size_t)row * C);

    float4 xv = x4[threadIdx.x];                  // 256 threads * 4 = 1024
    float z[4] = {xv.x * 0.5f, xv.y * 0.5f, xv.z * 0.5f, xv.w * 0.5f};
    float m = fmaxf(fmaxf(z[0], z[1]), fmaxf(z[2], z[3]));
    m = blockReduceMax(m);

    float e[4], s = 0.f;
#pragma unroll
    for (int k = 0; k < 4; k++) { e[k] = expf(z[k] - m); s += e[k]; }
    s = blockReduceSum(s);
    float inv = 1.0f / s;

    __half2 h0 = __floats2half2_rn(e[0] * inv, e[1] * inv);
    __half2 h1 = __floats2half2_rn(e[2] * inv, e[3] * inv);
    uint2 pack = make_uint2(*(unsigned*)&h0, *(unsigned*)&h1);
    ((uint2*)(outh + (size_t)row * (C / 2)))[threadIdx.x] = pack;
}

// ---------------- pairwise L1 distance + K = exp(-W/eps) + KT ----------------
// Identity: softmax rows sum to 1 ->  W[i][j] = 2 - 2 * sum_c min(ps, pt).
// fp16x2 packing: 2 channels per register; per channel-pair one __vminu2
// (alu pipe; valid fp16 min since all values positive) + one HADD2 (fma
// pipe) covers 2 element-pairs -> ~0.67 issue slots per element-pair incl.
// LDS and promotes (vs 2.09 fp32). fp16 accumulators promoted to fp32 every
// 32 channels. Tile 128(i) x 64(j), 256 threads, 8x4 register tile.
// Double-buffered smem, prefetch-under-compute, one sync per chunk.
__global__ void __launch_bounds__(256, 2) wxy_kernel() {
    __shared__ __align__(16) unsigned As[2][8][128];  // [buf][cpair][i]
    __shared__ __align__(16) unsigned Bs[2][8][64];   // [buf][cpair][j]

    const int i0 = blockIdx.y * 128;
    const int j0 = blockIdx.x * 64;
    const int tid = threadIdx.x;
    const int tx = tid & 15;        // j group: cols j0 + tx*4 .. +3
    const int ty = tid >> 4;        // i group: rows i0 + ty*8 .. +7

    // A staging: thread t loads 16B (4 half2 = 8 channels) of row (t&127),
    // channel-half (t>>7); 4 STS.32, conflict-free (addr = row mod 128).
    const int arow = tid & 127, ahalf = tid >> 7;
    // B staging: thread t loads 8B (2 half2) of row (t&63), quarter (t>>6).
    const int brow = tid & 63,  bq   = tid >> 6;

    const unsigned* pa = g_psh + (size_t)(i0 + arow) * (C / 2) + ahalf * 4;
    const unsigned* pb = g_pth + (size_t)(j0 + brow) * (C / 2) + bq * 2;

    float    accf[8][4];
    unsigned acch[8][4];
#pragma unroll
    for (int m = 0; m < 8; m++)
#pragma unroll
        for (int n = 0; n < 4; n++) { accf[m][n] = 0.f; acch[m][n] = 0u; }

    // Prologue: chunk 0 into buffer 0.
    {
        uint4 a4 = *(const uint4*)(pa);
        uint2 b2 = *(const uint2*)(pb);
        As[0][ahalf * 4 + 0][arow] = a4.x;  As[0][ahalf * 4 + 1][arow] = a4.y;
        As[0][ahalf * 4 + 2][arow] = a4.z;  As[0][ahalf * 4 + 3][arow] = a4.w;
        Bs[0][bq * 2 + 0][brow] = b2.x;     Bs[0][bq * 2 + 1][brow] = b2.y;
    }
    __syncthreads();

    int cur = 0;
#pragma unroll 2
    for (int ci = 0; ci < 64; ci++) {     // 64 chunks of 16 channels
        const bool more = (ci + 1 < 64);
        uint4 aN; uint2 bN;
        if (more) {                       // prefetch next chunk (8 half2 stride)
            aN = *(const uint4*)(pa + (ci + 1) * 8);
            bN = *(const uint2*)(pb + (ci + 1) * 8);
        }

#pragma unroll
        for (int cp = 0; cp < 8; cp++) {  // 8 channel-pairs per chunk
            uint4 a01 = *(const uint4*)&As[cur][cp][ty * 8];
            uint4 a23 = *(const uint4*)&As[cur][cp][ty * 8 + 4];
            uint4 bb  = *(const uint4*)&Bs[cur][cp][tx * 4];
            unsigned a[8] = {a01.x, a01.y, a01.z, a01.w, a23.x, a23.y, a23.z, a23.w};
            unsigned b[4] = {bb.x, bb.y, bb.z, bb.w};
#pragma unroll
            for (int m = 0; m < 8; m++)
#pragma unroll
                for (int n = 0; n < 4; n++) {
                    unsigned mn = __vminu2(a[m], b[n]);   // fp16x2 min (positive vals)
                    __half2 hs = __hadd2(*(__half2*)&acch[m][n], *(__half2*)&mn);
                    acch[m][n] = *(unsigned*)&hs;
                }
        }

        if (ci & 1) {                     // promote every 32 channels
#pragma unroll
            for (int m = 0; m < 8; m++)
#pragma unroll
                for (int n = 0; n < 4; n++) {
                    __half2 h = *(__half2*)&acch[m][n];
                    accf[m][n] += __low2float(h);
                    accf[m][n] += __high2float(h);
                    acch[m][n] = 0u;
                }
        }

        if (more) {
            int nxt = cur ^ 1;
            As[nxt][ahalf * 4 + 0][arow] = aN.x;  As[nxt][ahalf * 4 + 1][arow] = aN.y;
            As[nxt][ahalf * 4 + 2][arow] = aN.z;  As[nxt][ahalf * 4 + 3][arow] = aN.w;
            Bs[nxt][bq * 2 + 0][brow] = bN.x;     Bs[nxt][bq * 2 + 1][brow] = bN.y;
            __syncthreads();
            cur = nxt;
        }
    }

    // Epilogue: W and K row-major; K values overwrite accf in place.
#pragma unroll
    for (int m = 0; m < 8; m++) {
        int i = i0 + ty * 8 + m;
        size_t base = (size_t)i * B + j0 + tx * 4;
        float w0 = 2.0f - 2.0f * accf[m][0];
        float w1 = 2.0f - 2.0f * accf[m][1];
        float w2 = 2.0f - 2.0f * accf[m][2];
        float w3 = 2.0f - 2.0f * accf[m][3];
        *(float4*)&g_W[base] = make_float4(w0, w1, w2, w3);
        accf[m][0] = expf(-10.f * w0);
        accf[m][1] = expf(-10.f * w1);
        accf[m][2] = expf(-10.f * w2);
        accf[m][3] = expf(-10.f * w3);
        *(float4*)&g_K[base] = make_float4(accf[m][0], accf[m][1], accf[m][2], accf[m][3]);
    }
    // KT: for each j, the 8 i-values are contiguous -> two STG.128 per j.
#pragma unroll
    for (int n = 0; n < 4; n++) {
        int j = j0 + tx * 4 + n;
        size_t base = (size_t)j * B + i0 + ty * 8;
        *(float4*)&g_KT[base]     = make_float4(accf[0][n], accf[1][n], accf[2][n], accf[3][n]);
        *(float4*)&g_KT[base + 4] = make_float4(accf[4][n], accf[5][n], accf[6][n], accf[7][n]);
    }
}

// ---------------- persistent Sinkhorn + fused loss ----------------
__device__ __forceinline__ void grid_barrier() {
    __syncthreads();
    if (threadIdx.x == 0) {
        __threadfence();                                  // publish my writes
        unsigned t = atomicAdd(&g_bar, 1u) + 1u;
        unsigned target = ((t + NSM - 1u) / NSM) * NSM;   // end of this instance
        while (*(volatile unsigned*)&g_bar < target) __nanosleep(32);
        __threadfence();                                  // acquire others' writes
    }
    __syncthreads();
}

// Warp-per-row dot with x staged in smem: 16 independent LDG.128 per lane
// (MLP=16) against the L2-hot matrix + conflict-benign LDS for x.
__device__ __forceinline__ float warpDotRowS(const float* __restrict__ M,
                                             const float* __restrict__ xsh,
                                             int row, int lane) {
    const float4* M4 = (const float4*)(M + (size_t)row * B);
    const float4* x4 = (const float4*)xsh;
    float s = 0.f;
#pragma unroll
    for (int k = 0; k < 16; k++) {
        float4 m  = M4[lane + k * 32];
        float4 xv = x4[lane + k * 32];
        s += m.x * xv.x + m.y * xv.y + m.z * xv.z + m.w * xv.w;
    }
#pragma unroll
    for (int o = 16; o > 0; o >>= 1) s += __shfl_xor_sync(0xffffffffu, s, o);
    return s;
}

__global__ void __launch_bounds__(256) sinkhorn_kernel(float* __restrict__ out) {
    __shared__ __align__(16) float xsh[B];               // staged u or v (8KB)
    const int tid   = threadIdx.x;
    const int wid   = tid >> 5;
    const int lane  = tid & 31;
    const int wrow0 = blockIdx.x * 8 + wid;
    const int wstep = NSM * 8;

    for (int iter = 0; iter < 20; iter++) {
        // stage v (L2-coherent), then u = 1 / (K v)
        for (int i = tid; i < B; i += 256) xsh[i] = __ldcg(&g_v[i]);
        __syncthreads();
        for (int row = wrow0; row < B; row += wstep) {
            float s = warpDotRowS(g_K, xsh, row, lane);
            if (lane == 0) g_u[row] = 1.0f / s;
        }
        grid_barrier();
        // stage u, then v = 1 / (K^T u)
        for (int i = tid; i < B; i += 256) xsh[i] = __ldcg(&g_u[i]);
        __syncthreads();
        for (int row = wrow0; row < B; row += wstep) {
            float s = warpDotRowS(g_KT, xsh, row, lane);
            if (lane == 0) g_v[row] = 1.0f / s;
        }
        grid_barrier();
    }

    // ---- fused loss: 0.001 * sum_ij u_i K_ij W_ij v_j ----
    for (int i = tid; i < B; i += 256) xsh[i] = __ldcg(&g_v[i]);
    __syncthreads();
    for (int row = wrow0; row < B; row += wstep) {
        const float4* K4 = (const float4*)(g_K + (size_t)row * B);
        const float4* W4 = (const float4*)(g_W + (size_t)row * B);
        const float4* x4 = (const float4*)xsh;
        float s = 0.f;
#pragma unroll
        for (int k = 0; k < 16; k++) {
            float4 kk = K4[lane + k * 32];
            float4 ww = W4[lane + k * 32];
            float4 vv = x4[lane + k * 32];
            s += kk.x * ww.x * vv.x + kk.y * ww.y * vv.y
               + kk.z * ww.z * vv.z + kk.w * ww.w * vv.w;
        }
#pragma unroll
        for (int o = 16; o > 0; o >>= 1) s += __shfl_xor_sync(0xffffffffu, s, o);
        if (lane == 0) g_partial[row] = __ldcg(&g_u[row]) * s;
    }
    grid_barrier();

    if (blockIdx.x == 0) {                      // deterministic final reduce
        float s = 0.f;
        for (int i = tid; i < B; i += 256) s += __ldcg(&g_partial[i]);
        s = blockReduceSum(s);
        if (tid == 0) out[0] = 0.001f * s;
    }
}

// ---------------- launch ----------------
extern "C" void kernel_launch(void* const* d_in, const int* in_sizes, int n_in,
                              void* d_out, int out_size) {
    const float* y_s = (const float*)d_in[0];
    const float* y_t = (const float*)d_in[1];
    float* out = (float*)d_out;

    softmax_kernel<<<2 * B, 256>>>(y_s, y_t);
    wxy_kernel<<<dim3(B / 64, B / 128), 256>>>();
    sinkhorn_kernel<<<NSM, 256>>>(out);
}